// round 7
// baseline (speedup 1.0000x reference)
#include <cuda_runtime.h>
#include <stdint.h>

// Shapes fixed by the problem definition.
#define V_TOK   50000
#define D_DIM   300
#define H_DIM   32
#define C_DIM   3
#define B_BATCH 2048
#define L_SEQ   200

// Scratch: T = emb_table @ W1, [V_TOK, H_DIM] fp32 (6.4 MB). __device__ global
// array (no dynamic allocation allowed anywhere).
__device__ float g_T[V_TOK * H_DIM];

// ---------------------------------------------------------------------------
// Kernel A: T[v][h] = sum_d emb[v][d] * W1[d][h]
// One thread per token. D processed in chunks of DC staged through SMEM
// (coalesced global loads), W1 chunk staged in SMEM (broadcast LDS.64 reads).
// Inner product uses packed fma.rn.f32x2 (2 MACs / instr on the fp32 pipe).
// ---------------------------------------------------------------------------
#define TOK_PER_CTA 128
#define DC 60   // 300 = 5 * 60

__global__ __launch_bounds__(TOK_PER_CTA)
void gemm_T_kernel(const float* __restrict__ emb, const float* __restrict__ W1) {
    __shared__ float a_stage[TOK_PER_CTA][DC + 1];        // +1 pad: conflict-free column reads
    __shared__ __align__(16) float w_stage[DC][H_DIM];    // rows 128B-aligned -> LDS.64 ok

    const int tid  = threadIdx.x;
    const int lane = tid & 31;
    const int wid  = tid >> 5;
    const int v0   = blockIdx.x * TOK_PER_CTA;
    const int v    = v0 + tid;

    // 16 packed f32x2 accumulators = 32 fp32 outputs
    unsigned long long acc[16];
#pragma unroll
    for (int i = 0; i < 16; i++) acc[i] = 0ULL;   // bit pattern of (0.0f, 0.0f)

    for (int d0 = 0; d0 < D_DIM; d0 += DC) {
        __syncthreads();
        // Stage W1 chunk: contiguous DC*H region starting at d0*H
        for (int i = tid; i < DC * H_DIM; i += TOK_PER_CTA)
            ((float*)w_stage)[i] = W1[d0 * H_DIM + i];
        // Stage emb rows for this CTA's tokens (coalesced: warp reads a row slice)
        for (int r = wid; r < TOK_PER_CTA; r += (TOK_PER_CTA / 32)) {
            int vv = v0 + r;
            if (vv < V_TOK) {
                for (int d = lane; d < DC; d += 32)
                    a_stage[r][d] = emb[vv * D_DIM + d0 + d];
            }
        }
        __syncthreads();

        if (v < V_TOK) {
#pragma unroll 4
            for (int k = 0; k < DC; k++) {
                float a = a_stage[tid][k];
                unsigned long long a2;
                asm("mov.b64 %0, {%1, %1};" : "=l"(a2) : "f"(a));
                const unsigned long long* wrow =
                    (const unsigned long long*)&w_stage[k][0];
#pragma unroll
                for (int hp = 0; hp < 16; hp++) {
                    asm("fma.rn.f32x2 %0, %1, %2, %0;"
                        : "+l"(acc[hp]) : "l"(a2), "l"(wrow[hp]));
                }
            }
        }
    }

    if (v < V_TOK) {
        float out[H_DIM];
#pragma unroll
        for (int hp = 0; hp < 16; hp++) {
            unsigned int lo, hi;
            asm("mov.b64 {%0, %1}, %2;" : "=r"(lo), "=r"(hi) : "l"(acc[hp]));
            out[2 * hp]     = __uint_as_float(lo);
            out[2 * hp + 1] = __uint_as_float(hi);
        }
        // Row is 128B and 16B-aligned: 8x STG.128, lanes cover a contiguous 4KB span
        float4* dst = (float4*)&g_T[(size_t)v * H_DIM];
#pragma unroll
        for (int j = 0; j < 8; j++)
            dst[j] = make_float4(out[4 * j], out[4 * j + 1],
                                 out[4 * j + 2], out[4 * j + 3]);
    }
}

// ---------------------------------------------------------------------------
// Kernel B: per batch row b:
//   s[h]   = sum_{l<L} T[x[b][l]][h]
//   hval   = relu(s[h] / len[b] + b1[h])
//   out[c] = b2[c] + sum_h hval * W2[h][c]
// One warp per batch row, lane = h. 4-way split accumulators for MLP.
// ---------------------------------------------------------------------------
__global__ __launch_bounds__(256)
void gather_mlp_kernel(const int* __restrict__ x,
                       const int* __restrict__ lengths,
                       const float* __restrict__ b1,
                       const float* __restrict__ W2,
                       const float* __restrict__ b2,
                       float* __restrict__ out) {
    const int lane = threadIdx.x & 31;
    const int wid  = threadIdx.x >> 5;
    const int b    = blockIdx.x * 8 + wid;
    if (b >= B_BATCH) return;

    const int* __restrict__ xr = x + (size_t)b * L_SEQ;

    float acc0 = 0.f, acc1 = 0.f, acc2 = 0.f, acc3 = 0.f;
#pragma unroll 2
    for (int l = 0; l < L_SEQ; l += 4) {
        int i0 = __ldg(&xr[l + 0]);
        int i1 = __ldg(&xr[l + 1]);
        int i2 = __ldg(&xr[l + 2]);
        int i3 = __ldg(&xr[l + 3]);
        acc0 += __ldg(&g_T[(size_t)i0 * H_DIM + lane]);
        acc1 += __ldg(&g_T[(size_t)i1 * H_DIM + lane]);
        acc2 += __ldg(&g_T[(size_t)i2 * H_DIM + lane]);
        acc3 += __ldg(&g_T[(size_t)i3 * H_DIM + lane]);
    }
    float s = (acc0 + acc1) + (acc2 + acc3);

    float len  = (float)__ldg(&lengths[b]);
    float hval = fmaxf(s / len + __ldg(&b1[lane]), 0.0f);

    float p0 = hval * __ldg(&W2[lane * C_DIM + 0]);
    float p1 = hval * __ldg(&W2[lane * C_DIM + 1]);
    float p2 = hval * __ldg(&W2[lane * C_DIM + 2]);
#pragma unroll
    for (int off = 16; off; off >>= 1) {
        p0 += __shfl_down_sync(0xffffffffu, p0, off);
        p1 += __shfl_down_sync(0xffffffffu, p1, off);
        p2 += __shfl_down_sync(0xffffffffu, p2, off);
    }
    if (lane == 0) {
        out[b * C_DIM + 0] = p0 + __ldg(&b2[0]);
        out[b * C_DIM + 1] = p1 + __ldg(&b2[1]);
        out[b * C_DIM + 2] = p2 + __ldg(&b2[2]);
    }
}

// ---------------------------------------------------------------------------
// Launch: inputs in metadata order: x, lengths, emb_table, W1, b1, W2, b2
// ---------------------------------------------------------------------------
extern "C" void kernel_launch(void* const* d_in, const int* in_sizes, int n_in,
                              void* d_out, int out_size) {
    const int*   x       = (const int*)d_in[0];
    const int*   lengths = (const int*)d_in[1];
    const float* emb     = (const float*)d_in[2];
    const float* W1      = (const float*)d_in[3];
    const float* b1      = (const float*)d_in[4];
    const float* W2      = (const float*)d_in[5];
    const float* b2      = (const float*)d_in[6];
    float*       out     = (float*)d_out;

    (void)in_sizes; (void)n_in; (void)out_size;

    gemm_T_kernel<<<(V_TOK + TOK_PER_CTA - 1) / TOK_PER_CTA, TOK_PER_CTA>>>(emb, W1);
    gather_mlp_kernel<<<(B_BATCH + 7) / 8, 256>>>(x, lengths, b1, W2, b2, out);
}

// round 8
// speedup vs baseline: 1.1611x; 1.1611x over previous
#include <cuda_runtime.h>
#include <stdint.h>

// Shapes fixed by the problem definition.
#define V_TOK   50000
#define D_DIM   300
#define H_DIM   32
#define C_DIM   3
#define B_BATCH 2048
#define L_SEQ   200

// Scratch: T = emb_table @ W1, [V_TOK, H_DIM] fp32 (6.4 MB).
__device__ float g_T[V_TOK * H_DIM];

// ---- packed f32x2 helpers (sm_103a FFMA2 — only reachable via PTX) ----
__device__ __forceinline__ unsigned long long pack2(float lo, float hi) {
    unsigned long long r;
    asm("mov.b64 %0, {%1, %2};" : "=l"(r) : "f"(lo), "f"(hi));
    return r;
}
__device__ __forceinline__ void unpack2(unsigned long long v, float& lo, float& hi) {
    asm("mov.b64 {%0, %1}, %2;" : "=f"(lo), "=f"(hi) : "l"(v));
}
__device__ __forceinline__ void ffma2(unsigned long long& acc,
                                      unsigned long long a,
                                      unsigned long long b) {
    asm("fma.rn.f32x2 %0, %1, %2, %0;" : "+l"(acc) : "l"(a), "l"(b));
}

// ---------------------------------------------------------------------------
// Kernel A: T = emb_table [V,300] @ W1 [300,32]
// CTA = 128 threads = 4 warps, 128 tokens. Warp w owns tokens [32w, 32w+32).
// Thread tile: 4 tokens x 8 h  (lane: tg = lane>>2 -> token quad, hg = lane&3
// -> h octet). Per d-step: 1 LDS.128 (a, 4 contiguous tokens, d-major stage)
// + 2 LDS.128 (w, broadcast) + 4 packs + 16 FFMA2 = 23 instrs / 128 MACs.
// ---------------------------------------------------------------------------
#define TOK_PER_CTA 128
#define DC 60            // 300 = 5 * 60
#define APAD 132         // 128 + 4: breaks the STS transpose conflict, keeps
                         // rows 16B-aligned (132*4 = 528 % 16 == 0)

__global__ __launch_bounds__(TOK_PER_CTA)
void gemm_T_kernel(const float* __restrict__ emb, const float* __restrict__ W1) {
    __shared__ __align__(16) float a_stage[DC][APAD];   // d-major token tile
    __shared__ __align__(16) float w_stage[DC][H_DIM];

    const int tid  = threadIdx.x;
    const int lane = tid & 31;
    const int wid  = tid >> 5;
    const int v0   = blockIdx.x * TOK_PER_CTA;

    const int tg      = lane >> 2;               // 0..7  -> token quad in warp
    const int hg      = lane & 3;                // 0..3  -> h octet
    const int tok_off = wid * 32 + tg * 4;       // CTA-local first token
    const int h0      = hg * 8;

    unsigned long long acc[4][4];                // [token][h-pair-pair]
#pragma unroll
    for (int t = 0; t < 4; t++)
#pragma unroll
        for (int p = 0; p < 4; p++) acc[t][p] = 0ULL;

    for (int d0 = 0; d0 < D_DIM; d0 += DC) {
        __syncthreads();
        // Stage W1 chunk (contiguous -> coalesced)
        for (int i = tid; i < DC * H_DIM; i += TOK_PER_CTA)
            ((float*)w_stage)[i] = W1[d0 * H_DIM + i];
        // Stage emb, transposed to d-major. Warp reads a row chunk coalesced,
        // scatters to column r (4-way STS bank conflict — staging only).
        for (int r = wid; r < TOK_PER_CTA; r += 4) {
            const int v = v0 + r;
            if (v < V_TOK) {
                const float* __restrict__ src = emb + (size_t)v * D_DIM + d0;
                for (int d = lane; d < DC; d += 32)
                    a_stage[d][r] = src[d];
            } else {
                for (int d = lane; d < DC; d += 32)
                    a_stage[d][r] = 0.0f;
            }
        }
        __syncthreads();

#pragma unroll 2
        for (int k = 0; k < DC; k++) {
            const float4 av  = *(const float4*)&a_stage[k][tok_off];
            const float4 wv0 = *(const float4*)&w_stage[k][h0];
            const float4 wv1 = *(const float4*)&w_stage[k][h0 + 4];
            unsigned long long w01[4];
            w01[0] = pack2(wv0.x, wv0.y);
            w01[1] = pack2(wv0.z, wv0.w);
            w01[2] = pack2(wv1.x, wv1.y);
            w01[3] = pack2(wv1.z, wv1.w);
            unsigned long long a2[4];
            a2[0] = pack2(av.x, av.x);
            a2[1] = pack2(av.y, av.y);
            a2[2] = pack2(av.z, av.z);
            a2[3] = pack2(av.w, av.w);
#pragma unroll
            for (int t = 0; t < 4; t++)
#pragma unroll
                for (int p = 0; p < 4; p++)
                    ffma2(acc[t][p], a2[t], w01[p]);
        }
    }

    // Epilogue: each thread writes 4 tokens x 8 h (2 x STG.128 per token)
#pragma unroll
    for (int t = 0; t < 4; t++) {
        const int v = v0 + tok_off + t;
        if (v < V_TOK) {
            float o[8];
#pragma unroll
            for (int p = 0; p < 4; p++) unpack2(acc[t][p], o[2 * p], o[2 * p + 1]);
            float4* dst = (float4*)&g_T[(size_t)v * H_DIM + h0];
            dst[0] = make_float4(o[0], o[1], o[2], o[3]);
            dst[1] = make_float4(o[4], o[5], o[6], o[7]);
        }
    }
}

// ---------------------------------------------------------------------------
// Kernel B: per batch row b:
//   s[h] = sum_l T[x[b][l]][h];  h = relu(s/len + b1);  out = h @ W2 + b2
// CTA = 256 threads = 8 warps = 4 rows x 2 warps (interleaved l).
// Indices pre-staged in SMEM (kills the dependent idx-LDG chain).
// ---------------------------------------------------------------------------
#define ROWS_PER_CTA 4

__global__ __launch_bounds__(256)
void gather_mlp_kernel(const int* __restrict__ x,
                       const int* __restrict__ lengths,
                       const float* __restrict__ b1,
                       const float* __restrict__ W2,
                       const float* __restrict__ b2,
                       float* __restrict__ out) {
    __shared__ int   sidx[ROWS_PER_CTA][L_SEQ];
    __shared__ float psum[8][H_DIM];

    const int tid  = threadIdx.x;
    const int lane = tid & 31;
    const int wid  = tid >> 5;
    const int row  = wid >> 1;        // 0..3 CTA-local batch row
    const int half = wid & 1;         // which l-interleave
    const int b    = blockIdx.x * ROWS_PER_CTA + row;

    // Stage all indices for this CTA's rows (coalesced)
    for (int i = tid; i < ROWS_PER_CTA * L_SEQ; i += 256)
        ((int*)sidx)[i] = x[(size_t)blockIdx.x * ROWS_PER_CTA * L_SEQ + i];
    __syncthreads();

    float a0 = 0.f, a1 = 0.f, a2 = 0.f, a3 = 0.f;
#pragma unroll 5
    for (int j = 0; j < L_SEQ / 2; j += 4) {
        const int i0 = sidx[row][half + 2 * (j + 0)];
        const int i1 = sidx[row][half + 2 * (j + 1)];
        const int i2 = sidx[row][half + 2 * (j + 2)];
        const int i3 = sidx[row][half + 2 * (j + 3)];
        a0 += __ldg(&g_T[(size_t)i0 * H_DIM + lane]);
        a1 += __ldg(&g_T[(size_t)i1 * H_DIM + lane]);
        a2 += __ldg(&g_T[(size_t)i2 * H_DIM + lane]);
        a3 += __ldg(&g_T[(size_t)i3 * H_DIM + lane]);
    }
    psum[wid][lane] = (a0 + a1) + (a2 + a3);
    __syncthreads();

    if (half == 0) {
        const float s    = psum[wid][lane] + psum[wid + 1][lane];
        const float len  = (float)__ldg(&lengths[b]);
        const float hval = fmaxf(s / len + __ldg(&b1[lane]), 0.0f);

        float p0 = hval * __ldg(&W2[lane * C_DIM + 0]);
        float p1 = hval * __ldg(&W2[lane * C_DIM + 1]);
        float p2 = hval * __ldg(&W2[lane * C_DIM + 2]);
#pragma unroll
        for (int off = 16; off; off >>= 1) {
            p0 += __shfl_down_sync(0xffffffffu, p0, off);
            p1 += __shfl_down_sync(0xffffffffu, p1, off);
            p2 += __shfl_down_sync(0xffffffffu, p2, off);
        }
        if (lane == 0) {
            out[b * C_DIM + 0] = p0 + __ldg(&b2[0]);
            out[b * C_DIM + 1] = p1 + __ldg(&b2[1]);
            out[b * C_DIM + 2] = p2 + __ldg(&b2[2]);
        }
    }
}

// ---------------------------------------------------------------------------
// Launch: inputs in metadata order: x, lengths, emb_table, W1, b1, W2, b2
// ---------------------------------------------------------------------------
extern "C" void kernel_launch(void* const* d_in, const int* in_sizes, int n_in,
                              void* d_out, int out_size) {
    const int*   x       = (const int*)d_in[0];
    const int*   lengths = (const int*)d_in[1];
    const float* emb     = (const float*)d_in[2];
    const float* W1      = (const float*)d_in[3];
    const float* b1      = (const float*)d_in[4];
    const float* W2      = (const float*)d_in[5];
    const float* b2      = (const float*)d_in[6];
    float*       out     = (float*)d_out;

    (void)in_sizes; (void)n_in; (void)out_size;

    gemm_T_kernel<<<(V_TOK + TOK_PER_CTA - 1) / TOK_PER_CTA, TOK_PER_CTA>>>(emb, W1);
    gather_mlp_kernel<<<B_BATCH / ROWS_PER_CTA, 256>>>(x, lengths, b1, W2, b2, out);
}

// round 9
// speedup vs baseline: 1.5962x; 1.3747x over previous
#include <cuda_runtime.h>
#include <stdint.h>

// Shapes fixed by the problem definition.
#define V_TOK   50000
#define D_DIM   300
#define H_DIM   32
#define C_DIM   3
#define B_BATCH 2048
#define L_SEQ   200

// Scratch: T = emb_table @ W1, [V_TOK, H_DIM] fp32 (6.4 MB).
__device__ float g_T[V_TOK * H_DIM];

// ---- packed f32x2 helpers (sm_103a FFMA2 — only reachable via PTX) ----
__device__ __forceinline__ unsigned long long pack2(float lo, float hi) {
    unsigned long long r;
    asm("mov.b64 %0, {%1, %2};" : "=l"(r) : "f"(lo), "f"(hi));
    return r;
}
__device__ __forceinline__ void unpack2(unsigned long long v, float& lo, float& hi) {
    asm("mov.b64 {%0, %1}, %2;" : "=f"(lo), "=f"(hi) : "l"(v));
}
__device__ __forceinline__ void ffma2(unsigned long long& acc,
                                      unsigned long long a,
                                      unsigned long long b) {
    asm("fma.rn.f32x2 %0, %1, %2, %0;" : "+l"(acc) : "l"(a), "l"(b));
}
__device__ __forceinline__ float4 add4(float4 a, float4 b) {
    return make_float4(a.x + b.x, a.y + b.y, a.z + b.z, a.w + b.w);
}

// ---------------------------------------------------------------------------
// Kernel A: T = emb_table [V,300] @ W1 [300,32]
// CTA = 256 threads = 8 warps = 4 token-groups (16 tokens each) x 2 D-halves.
// Thread tile: 2 tokens x 8 h. Per k-step: 1 LDS.64 (a) + 2 LDS.128 (w,
// broadcast) + 3 packs + 8 FFMA2 = ~17 instrs / 64 MACs.
// D processed in 5 chunks of 60; each warp covers 30 k's of its half.
// D-half partials combined via padded smem buffer.
// Occupancy target: grid 782, ~4 CTAs/SM -> ~8 warps/SMSP (vs 2.6 before).
// ---------------------------------------------------------------------------
#define TOK_CTA 64
#define DC      60           // 300 = 5 * 60
#define DQ_LEN  30           // DC / 2 per warp-half
#define APAD    68           // 64+4: breaks staging STS conflict, mult of 4

__global__ __launch_bounds__(256)
void gemm_T_kernel(const float* __restrict__ emb, const float* __restrict__ W1) {
    __shared__ __align__(16) float a_stage[DC][APAD];     // d-major token tile
    __shared__ __align__(16) float w_stage[DC][H_DIM];
    __shared__ __align__(16) float red[TOK_CTA * 4][20];  // [tok*4+hg][dq*8+8], pad 20

    const int tid  = threadIdx.x;
    const int lane = tid & 31;
    const int wid  = tid >> 5;
    const int tg2  = wid & 3;          // token group 0..3 (16 tokens)
    const int dq   = wid >> 2;         // d-half 0/1
    const int v0   = blockIdx.x * TOK_CTA;

    const int tg      = lane >> 2;     // 0..7 -> token pair in group
    const int hg      = lane & 3;      // 0..3 -> h octet
    const int tok_off = tg2 * 16 + tg * 2;
    const int h0      = hg * 8;

    unsigned long long acc[2][4];      // [token][h-pair-pair]
#pragma unroll
    for (int t = 0; t < 2; t++)
#pragma unroll
        for (int p = 0; p < 4; p++) acc[t][p] = 0ULL;

#pragma unroll 1
    for (int c = 0; c < 5; c++) {
        const int d0 = c * DC;
        __syncthreads();
        // Stage W1 chunk (contiguous -> coalesced)
        for (int i = tid; i < DC * H_DIM; i += 256)
            ((float*)w_stage)[i] = W1[d0 * H_DIM + i];
        // Stage emb transposed to d-major: warp per row set, coalesced LDG
        for (int r = wid; r < TOK_CTA; r += 8) {
            const int v = v0 + r;
            if (v < V_TOK) {
                const float* __restrict__ src = emb + (size_t)v * D_DIM + d0;
                a_stage[lane][r] = src[lane];
                if (lane + 32 < DC) a_stage[lane + 32][r] = src[lane + 32];
            } else {
                a_stage[lane][r] = 0.0f;
                if (lane + 32 < DC) a_stage[lane + 32][r] = 0.0f;
            }
        }
        __syncthreads();

        const int kbeg = dq * DQ_LEN;
#pragma unroll
        for (int kk = 0; kk < DQ_LEN; kk++) {
            const int k = kbeg + kk;
            const float2 av  = *(const float2*)&a_stage[k][tok_off];
            const float4 wv0 = *(const float4*)&w_stage[k][h0];
            const float4 wv1 = *(const float4*)&w_stage[k][h0 + 4];
            unsigned long long w01[4];
            w01[0] = pack2(wv0.x, wv0.y);
            w01[1] = pack2(wv0.z, wv0.w);
            w01[2] = pack2(wv1.x, wv1.y);
            w01[3] = pack2(wv1.z, wv1.w);
            const unsigned long long a0 = pack2(av.x, av.x);
            const unsigned long long a1 = pack2(av.y, av.y);
#pragma unroll
            for (int p = 0; p < 4; p++) ffma2(acc[0][p], a0, w01[p]);
#pragma unroll
            for (int p = 0; p < 4; p++) ffma2(acc[1][p], a1, w01[p]);
        }
    }

    // Write D-half partials to smem: red[(tok)*4+hg][dq*8 .. +8]
#pragma unroll
    for (int t = 0; t < 2; t++) {
        float o[8];
#pragma unroll
        for (int p = 0; p < 4; p++) unpack2(acc[t][p], o[2 * p], o[2 * p + 1]);
        float* dst = &red[(tok_off + t) * 4 + hg][dq * 8];
        ((float4*)dst)[0] = make_float4(o[0], o[1], o[2], o[3]);
        ((float4*)dst)[1] = make_float4(o[4], o[5], o[6], o[7]);
    }
    __syncthreads();

    // Combine halves: thread tid owns output chunk (tok = tid>>2, h octet = tid&3)
    {
        const float4* r4 = (const float4*)&red[tid][0];  // row = 20 words = 80B, 16B aligned
        const float4 s0 = add4(r4[0], r4[2]);            // dq0 words 0..7, dq1 words 8..15
        const float4 s1 = add4(r4[1], r4[3]);
        const int v = v0 + (tid >> 2);
        if (v < V_TOK) {
            float4* dst = (float4*)&g_T[(size_t)v * H_DIM + (tid & 3) * 8];
            dst[0] = s0;
            dst[1] = s1;
        }
    }
}

// ---------------------------------------------------------------------------
// Kernel B: per batch row b:
//   s[h] = sum_l T[x[b][l]][h];  h = relu(s/len + b1);  out = h @ W2 + b2
// CTA = 256 threads = 8 warps = 2 rows x 4 warps (l strided by 4).
// 10 independent accumulator chains per warp (MLP ~10), indices staged in smem.
// Grid 1024 -> ~55 warps/SM.
// ---------------------------------------------------------------------------
#define ROWS_PER_CTA 2

__global__ __launch_bounds__(256)
void gather_mlp_kernel(const int* __restrict__ x,
                       const int* __restrict__ lengths,
                       const float* __restrict__ b1,
                       const float* __restrict__ W2,
                       const float* __restrict__ b2,
                       float* __restrict__ out) {
    __shared__ int   sidx[ROWS_PER_CTA][L_SEQ];
    __shared__ float psum[8][H_DIM];

    const int tid  = threadIdx.x;
    const int lane = tid & 31;
    const int wid  = tid >> 5;
    const int row  = wid >> 2;        // 0..1 CTA-local batch row
    const int q    = wid & 3;         // l-stripe
    const int b    = blockIdx.x * ROWS_PER_CTA + row;

    // Stage all indices for this CTA's rows (coalesced)
    for (int i = tid; i < ROWS_PER_CTA * L_SEQ; i += 256)
        ((int*)sidx)[i] = x[(size_t)blockIdx.x * ROWS_PER_CTA * L_SEQ + i];
    __syncthreads();

    float acc[10];
#pragma unroll
    for (int u = 0; u < 10; u++) acc[u] = 0.0f;

#pragma unroll 1
    for (int j = 0; j < 5; j++) {
#pragma unroll
        for (int u = 0; u < 10; u++) {
            const int l   = q + 4 * (j * 10 + u);     // 50 l's per warp
            const int idx = sidx[row][l];
            acc[u] += __ldg(&g_T[(size_t)idx * H_DIM + lane]);
        }
    }
    float s = ((acc[0] + acc[1]) + (acc[2] + acc[3])) +
              ((acc[4] + acc[5]) + (acc[6] + acc[7])) + (acc[8] + acc[9]);
    psum[wid][lane] = s;
    __syncthreads();

    if (q == 0) {
        const float st = (psum[wid][lane] + psum[wid + 1][lane]) +
                         (psum[wid + 2][lane] + psum[wid + 3][lane]);
        const float len  = (float)__ldg(&lengths[b]);
        const float hval = fmaxf(st / len + __ldg(&b1[lane]), 0.0f);

        float p0 = hval * __ldg(&W2[lane * C_DIM + 0]);
        float p1 = hval * __ldg(&W2[lane * C_DIM + 1]);
        float p2 = hval * __ldg(&W2[lane * C_DIM + 2]);
#pragma unroll
        for (int off = 16; off; off >>= 1) {
            p0 += __shfl_down_sync(0xffffffffu, p0, off);
            p1 += __shfl_down_sync(0xffffffffu, p1, off);
            p2 += __shfl_down_sync(0xffffffffu, p2, off);
        }
        if (lane == 0) {
            out[b * C_DIM + 0] = p0 + __ldg(&b2[0]);
            out[b * C_DIM + 1] = p1 + __ldg(&b2[1]);
            out[b * C_DIM + 2] = p2 + __ldg(&b2[2]);
        }
    }
}

// ---------------------------------------------------------------------------
// Launch: inputs in metadata order: x, lengths, emb_table, W1, b1, W2, b2
// ---------------------------------------------------------------------------
extern "C" void kernel_launch(void* const* d_in, const int* in_sizes, int n_in,
                              void* d_out, int out_size) {
    const int*   x       = (const int*)d_in[0];
    const int*   lengths = (const int*)d_in[1];
    const float* emb     = (const float*)d_in[2];
    const float* W1      = (const float*)d_in[3];
    const float* b1      = (const float*)d_in[4];
    const float* W2      = (const float*)d_in[5];
    const float* b2      = (const float*)d_in[6];
    float*       out     = (float*)d_out;

    (void)in_sizes; (void)n_in; (void)out_size;

    gemm_T_kernel<<<(V_TOK + TOK_CTA - 1) / TOK_CTA, 256>>>(emb, W1);
    gather_mlp_kernel<<<B_BATCH / ROWS_PER_CTA, 256>>>(x, lengths, b1, W2, b2, out);
}

// round 10
// speedup vs baseline: 2.0806x; 1.3035x over previous
#include <cuda_runtime.h>
#include <stdint.h>

// Shapes fixed by the problem definition.
#define V_TOK   50000
#define D_DIM   300
#define H_DIM   32
#define C_DIM   3
#define B_BATCH 2048
#define L_SEQ   200

// Scratch: T = emb_table @ W1, [V_TOK, H_DIM] fp32 (6.4 MB).
__device__ float g_T[V_TOK * H_DIM];

// ---- packed f32x2 helpers (sm_103a FFMA2 — only reachable via PTX) ----
__device__ __forceinline__ unsigned long long pack2(float lo, float hi) {
    unsigned long long r;
    asm("mov.b64 %0, {%1, %2};" : "=l"(r) : "f"(lo), "f"(hi));
    return r;
}
__device__ __forceinline__ void unpack2(unsigned long long v, float& lo, float& hi) {
    asm("mov.b64 {%0, %1}, %2;" : "=f"(lo), "=f"(hi) : "l"(v));
}
__device__ __forceinline__ void ffma2(unsigned long long& acc,
                                      unsigned long long a,
                                      unsigned long long b) {
    asm("fma.rn.f32x2 %0, %1, %2, %0;" : "+l"(acc) : "l"(a), "l"(b));
}
__device__ __forceinline__ float4 add4(float4 a, float4 b) {
    return make_float4(a.x + b.x, a.y + b.y, a.z + b.z, a.w + b.w);
}
__device__ __forceinline__ uint32_t smem_u32(const void* p) {
    uint32_t a;
    asm("{ .reg .u64 t; cvta.to.shared.u64 t, %1; cvt.u32.u64 %0, t; }"
        : "=r"(a) : "l"(p));
    return a;
}

// ---------------------------------------------------------------------------
// Kernel A: T = emb_table [V,300] @ W1 [300,32]
// CTA = 256 thr = 8 warps = 4 token-groups (16 tok) x 2 D-halves; thread tile
// 2 tokens x 8 h (tokens tg and tg+8 -> conflict-free LDS.32 at row stride 60).
// cp.async double-buffered staging: DRAM latency hidden behind the mainloop.
// Per k-step: 2 LDS.32 + 2 LDS.128(bcast) + 2 MOV + 8 FFMA2 = 14 instr/64 MAC.
// ---------------------------------------------------------------------------
#define TOK_CTA 64
#define DC      60           // 300 = 5 * 60
#define NCHUNK  5
#define DQ      30           // DC / 2 per warp d-half
#define ASEG    (DC / 4)     // 15 x 16B segments per row

__global__ __launch_bounds__(256)
void gemm_T_kernel(const float* __restrict__ emb, const float* __restrict__ W1) {
    __shared__ __align__(16) float a_stage[2][TOK_CTA][DC];   // 30720 B
    __shared__ __align__(16) float w_stage[2][DC][H_DIM];     // 15360 B

    const int tid  = threadIdx.x;
    const int lane = tid & 31;
    const int wid  = tid >> 5;
    const int tg2  = wid & 3;          // token group (16 tokens)
    const int dq   = wid >> 2;         // d-half 0/1
    const int tg   = lane >> 2;        // 0..7
    const int hg   = lane & 3;         // 0..3
    const int tok0 = tg2 * 16 + tg;
    const int tok1 = tok0 + 8;
    const int h0   = hg * 8;
    const int v0   = blockIdx.x * TOK_CTA;

    const uint32_t a_smem = smem_u32(&a_stage[0][0][0]);
    const uint32_t w_smem = smem_u32(&w_stage[0][0][0]);

#define STAGE(c, buf) do {                                                     \
        for (int i = tid; i < TOK_CTA * ASEG; i += 256) {                      \
            const int row = i / ASEG;                                          \
            const int seg = i - row * ASEG;                                    \
            if (v0 + row < V_TOK) {                                            \
                const float* g = emb + (size_t)(v0 + row) * D_DIM              \
                                     + (c) * DC + seg * 4;                     \
                const uint32_t s = a_smem +                                    \
                    (uint32_t)(((buf) * TOK_CTA * DC + row * DC + seg * 4) * 4);\
                asm volatile("cp.async.ca.shared.global [%0], [%1], 16;"       \
                             :: "r"(s), "l"(g));                               \
            }                                                                  \
        }                                                                      \
        for (int i = tid; i < DC * H_DIM / 4; i += 256) {                      \
            const float* g = W1 + (c) * DC * H_DIM + i * 4;                    \
            const uint32_t s = w_smem +                                        \
                (uint32_t)(((buf) * DC * H_DIM + i * 4) * 4);                  \
            asm volatile("cp.async.ca.shared.global [%0], [%1], 16;"           \
                         :: "r"(s), "l"(g));                                   \
        }                                                                      \
        asm volatile("cp.async.commit_group;");                                \
    } while (0)

    unsigned long long acc[2][4];      // [token][h-pair-pair]
#pragma unroll
    for (int t = 0; t < 2; t++)
#pragma unroll
        for (int p = 0; p < 4; p++) acc[t][p] = 0ULL;

    STAGE(0, 0);

#pragma unroll 1
    for (int c = 0; c < NCHUNK; c++) {
        const int buf = c & 1;
        if (c + 1 < NCHUNK) {
            STAGE(c + 1, buf ^ 1);
            asm volatile("cp.async.wait_group 1;");   // chunk c complete
        } else {
            asm volatile("cp.async.wait_group 0;");
        }
        __syncthreads();

        const float* __restrict__ ap = &a_stage[buf][0][dq * DQ];
        const float* __restrict__ wp = &w_stage[buf][dq * DQ][0];
#pragma unroll
        for (int kk = 0; kk < DQ; kk++) {
            const float a0v = ap[tok0 * DC + kk];
            const float a1v = ap[tok1 * DC + kk];
            const float4 wv0 = *(const float4*)&wp[kk * H_DIM + h0];
            const float4 wv1 = *(const float4*)&wp[kk * H_DIM + h0 + 4];
            unsigned long long w01[4];
            w01[0] = pack2(wv0.x, wv0.y);
            w01[1] = pack2(wv0.z, wv0.w);
            w01[2] = pack2(wv1.x, wv1.y);
            w01[3] = pack2(wv1.z, wv1.w);
            const unsigned long long a0 = pack2(a0v, a0v);
            const unsigned long long a1 = pack2(a1v, a1v);
#pragma unroll
            for (int p = 0; p < 4; p++) ffma2(acc[0][p], a0, w01[p]);
#pragma unroll
            for (int p = 0; p < 4; p++) ffma2(acc[1][p], a1, w01[p]);
        }
        __syncthreads();   // compute(c) done before STAGE(c+2) reuses this buf
    }

    // ---- Epilogue: combine d-halves via smem (overlay on a_stage) ----
    // red[token][dq*32 + h], row stride 68 words -> conflict-free STS.128
    float (*red)[68] = reinterpret_cast<float (*)[68]>(&a_stage[0][0][0]);

#pragma unroll
    for (int t = 0; t < 2; t++) {
        float o[8];
#pragma unroll
        for (int p = 0; p < 4; p++) unpack2(acc[t][p], o[2 * p], o[2 * p + 1]);
        const int tk = (t == 0) ? tok0 : tok1;
        float4* d = (float4*)&red[tk][dq * 32 + h0];
        d[0] = make_float4(o[0], o[1], o[2], o[3]);
        d[1] = make_float4(o[4], o[5], o[6], o[7]);
    }
    __syncthreads();

    {
        const int tt = tid >> 2;          // CTA-local token
        const int hq = tid & 3;           // h octet
        const float4* r0 = (const float4*)&red[tt][hq * 8];
        const float4* r1 = (const float4*)&red[tt][32 + hq * 8];
        const float4 s0 = add4(r0[0], r1[0]);
        const float4 s1 = add4(r0[1], r1[1]);
        const int v = v0 + tt;
        if (v < V_TOK) {
            float4* dst = (float4*)&g_T[(size_t)v * H_DIM + hq * 8];
            dst[0] = s0;
            dst[1] = s1;
        }
    }
#undef STAGE
}

// ---------------------------------------------------------------------------
// Kernel B: per batch row b:
//   s[h] = sum_l T[x[b][l]][h];  h = relu(s/len + b1);  out = h @ W2 + b2
// CTA = 256 threads = 8 warps = 2 rows x 4 warps (l strided by 4).
// 10 independent accumulator chains per warp, indices staged in smem.
// ---------------------------------------------------------------------------
#define ROWS_PER_CTA 2

__global__ __launch_bounds__(256)
void gather_mlp_kernel(const int* __restrict__ x,
                       const int* __restrict__ lengths,
                       const float* __restrict__ b1,
                       const float* __restrict__ W2,
                       const float* __restrict__ b2,
                       float* __restrict__ out) {
    __shared__ int   sidx[ROWS_PER_CTA][L_SEQ];
    __shared__ float psum[8][H_DIM];

    const int tid  = threadIdx.x;
    const int lane = tid & 31;
    const int wid  = tid >> 5;
    const int row  = wid >> 2;        // 0..1 CTA-local batch row
    const int q    = wid & 3;         // l-stripe
    const int b    = blockIdx.x * ROWS_PER_CTA + row;

    for (int i = tid; i < ROWS_PER_CTA * L_SEQ; i += 256)
        ((int*)sidx)[i] = x[(size_t)blockIdx.x * ROWS_PER_CTA * L_SEQ + i];
    __syncthreads();

    float acc[10];
#pragma unroll
    for (int u = 0; u < 10; u++) acc[u] = 0.0f;

#pragma unroll 1
    for (int j = 0; j < 5; j++) {
#pragma unroll
        for (int u = 0; u < 10; u++) {
            const int l   = q + 4 * (j * 10 + u);     // 50 l's per warp
            const int idx = sidx[row][l];
            acc[u] += __ldg(&g_T[(size_t)idx * H_DIM + lane]);
        }
    }
    float s = ((acc[0] + acc[1]) + (acc[2] + acc[3])) +
              ((acc[4] + acc[5]) + (acc[6] + acc[7])) + (acc[8] + acc[9]);
    psum[wid][lane] = s;
    __syncthreads();

    if (q == 0) {
        const float st = (psum[wid][lane] + psum[wid + 1][lane]) +
                         (psum[wid + 2][lane] + psum[wid + 3][lane]);
        const float len  = (float)__ldg(&lengths[b]);
        const float hval = fmaxf(st / len + __ldg(&b1[lane]), 0.0f);

        float p0 = hval * __ldg(&W2[lane * C_DIM + 0]);
        float p1 = hval * __ldg(&W2[lane * C_DIM + 1]);
        float p2 = hval * __ldg(&W2[lane * C_DIM + 2]);
#pragma unroll
        for (int off = 16; off; off >>= 1) {
            p0 += __shfl_down_sync(0xffffffffu, p0, off);
            p1 += __shfl_down_sync(0xffffffffu, p1, off);
            p2 += __shfl_down_sync(0xffffffffu, p2, off);
        }
        if (lane == 0) {
            out[b * C_DIM + 0] = p0 + __ldg(&b2[0]);
            out[b * C_DIM + 1] = p1 + __ldg(&b2[1]);
            out[b * C_DIM + 2] = p2 + __ldg(&b2[2]);
        }
    }
}

// ---------------------------------------------------------------------------
// Launch: inputs in metadata order: x, lengths, emb_table, W1, b1, W2, b2
// ---------------------------------------------------------------------------
extern "C" void kernel_launch(void* const* d_in, const int* in_sizes, int n_in,
                              void* d_out, int out_size) {
    const int*   x       = (const int*)d_in[0];
    const int*   lengths = (const int*)d_in[1];
    const float* emb     = (const float*)d_in[2];
    const float* W1      = (const float*)d_in[3];
    const float* b1      = (const float*)d_in[4];
    const float* W2      = (const float*)d_in[5];
    const float* b2      = (const float*)d_in[6];
    float*       out     = (float*)d_out;

    (void)in_sizes; (void)n_in; (void)out_size;

    gemm_T_kernel<<<(V_TOK + TOK_CTA - 1) / TOK_CTA, 256>>>(emb, W1);
    gather_mlp_kernel<<<B_BATCH / ROWS_PER_CTA, 256>>>(x, lengths, b1, W2, b2, out);
}

// round 12
// speedup vs baseline: 3.1793x; 1.5281x over previous
#include <cuda_runtime.h>
#include <cuda_bf16.h>
#include <stdint.h>

// Shapes fixed by the problem definition.
#define V_TOK   50000
#define D_DIM   300
#define H_DIM   32
#define C_DIM   3
#define B_BATCH 2048
#define L_SEQ   200

// Scratch: T = emb_table @ W1, [V_TOK, H_DIM] fp32 (6.4 MB).
__device__ float g_T[V_TOK * H_DIM];

// ===========================================================================
// Kernel A: T = emb @ W1 via warp-level bf16 HMMA (mma.sync m16n8k16) with
// 2-way error split:  D = Ahi*Bhi + Ahi*Blo + Alo*Bhi   (fp32 accumulate).
// NOTE: tcgen05 is ptxas-rejected here (harness lowers via compute_103, no
// 'a'); mma.sync/ldmatrix are baseline sm_80 PTX and compile fine.
// CTA = 128 threads = 4 warps; warp owns 32 token rows (2 x m16), N=32 (4 x n8).
// K = 300 padded to 320 = 5 chunks of 64 bf16. Per chunk: LDG fp32 -> split ->
// swizzled STS bf16 -> ldmatrix -> 96 mma/warp. Next chunk's LDG issued before
// the mma phase so DRAM latency overlaps tensor work.
// ===========================================================================
#define M_CTA    128
#define KCH      64
#define NCHUNK   5
#define A_TILE_B (M_CTA * KCH * 2)          // 16384 B per split
#define B_TILE_B (H_DIM * KCH * 2)          // 4096 B per (split, chunk)
#define SM_A     0                          // hi at 0, lo at A_TILE_B
#define SM_B     (2 * A_TILE_B)             // 32768
#define SM_NEED  (SM_B + 2 * NCHUNK * B_TILE_B)   // 73728
#define SM_DYN   (SM_NEED + 1024)

__device__ __forceinline__ uint32_t smem_u32(const void* p) {
    uint32_t a;
    asm("{ .reg .u64 t; cvta.to.shared.u64 t, %1; cvt.u32.u64 %0, t; }"
        : "=r"(a) : "l"(p));
    return a;
}
// SW128-style XOR swizzle for 128 B rows: bits[6:4] ^= bits[9:7]
__device__ __forceinline__ uint32_t sw(uint32_t off) {
    return off ^ ((off >> 3) & 0x70);
}
__device__ __forceinline__ uint32_t pack_bf2(__nv_bfloat16 lo, __nv_bfloat16 hi) {
    return (uint32_t)__bfloat16_as_ushort(lo) |
           ((uint32_t)__bfloat16_as_ushort(hi) << 16);
}

#define LDMX4(r, addr)                                                        \
    asm volatile("ldmatrix.sync.aligned.m8n8.x4.shared.b16 {%0,%1,%2,%3}, [%4];" \
                 : "=r"((r)[0]), "=r"((r)[1]), "=r"((r)[2]), "=r"((r)[3])     \
                 : "r"(addr))
#define LDMX2(r, addr)                                                        \
    asm volatile("ldmatrix.sync.aligned.m8n8.x2.shared.b16 {%0,%1}, [%2];"    \
                 : "=r"((r)[0]), "=r"((r)[1]) : "r"(addr))
#define MMA16816(d, a, b)                                                     \
    asm volatile("mma.sync.aligned.m16n8k16.row.col.f32.bf16.bf16.f32 "       \
                 "{%0,%1,%2,%3}, {%4,%5,%6,%7}, {%8,%9}, {%0,%1,%2,%3};"      \
                 : "+f"((d)[0]), "+f"((d)[1]), "+f"((d)[2]), "+f"((d)[3])     \
                 : "r"((a)[0]), "r"((a)[1]), "r"((a)[2]), "r"((a)[3]),        \
                   "r"((b)[0]), "r"((b)[1]))

extern __shared__ char dyn_smem[];

__global__ __launch_bounds__(128)
void gemm_T_tensor(const float* __restrict__ emb, const float* __restrict__ W1) {
    const uint32_t raw  = smem_u32(dyn_smem);
    const uint32_t base = (raw + 1023u) & ~1023u;
    char* const gb      = dyn_smem + (base - raw);

    const int tid  = threadIdx.x;
    const int lane = tid & 31;
    const int wid  = tid >> 5;
    const int v0   = blockIdx.x * M_CTA;

    // ---- Stage B = W1^T once: tile row = h (32 rows x 128 B), both splits ----
    for (int i = tid; i < NCHUNK * KCH * H_DIM; i += 128) {
        const int k = i >> 5;            // 0..319
        const int h = i & 31;
        const float v = (k < D_DIM) ? W1[k * H_DIM + h] : 0.0f;
        const __nv_bfloat16 bh = __float2bfloat16(v);
        const __nv_bfloat16 bl = __float2bfloat16(v - __bfloat162float(bh));
        const int chunk = k >> 6;
        const int kc    = k & 63;
        const uint32_t off = sw(((uint32_t)h << 7) + ((uint32_t)kc << 1));
        *(uint16_t*)(gb + SM_B + chunk * B_TILE_B + off) = __bfloat16_as_ushort(bh);
        *(uint16_t*)(gb + SM_B + (NCHUNK + chunk) * B_TILE_B + off) = __bfloat16_as_ushort(bl);
    }

    // Per-thread fixed (row, seg) for A staging: seg = tid&15, rows = tid>>4 + 8j
    const int seg   = tid & 15;
    const int rbase = tid >> 4;

    float4 f[16];
#define LOAD_CHUNK(c)                                                          \
    do {                                                                       \
        const int k0 = (c) * KCH + seg * 4;                                    \
        const bool kok = (k0 < D_DIM);                                         \
        _Pragma("unroll")                                                      \
        for (int j = 0; j < 16; j++) {                                         \
            const int v = v0 + rbase + j * 8;                                  \
            f[j] = (kok && v < V_TOK)                                          \
                 ? *(const float4*)(emb + (size_t)v * D_DIM + k0)              \
                 : make_float4(0.f, 0.f, 0.f, 0.f);                            \
        }                                                                      \
    } while (0)

    // ldmatrix per-lane address components
    const int warp_m0   = wid * 32;
    const uint32_t a_row = (uint32_t)(warp_m0 + (lane & 15));
    const uint32_t a_ks  = (uint32_t)((lane >> 4) << 3);      // 0 or 8
    const int bl16       = lane & 15;
    const uint32_t b_row = (uint32_t)(bl16 & 7);
    const uint32_t b_ks  = (uint32_t)((bl16 >> 3) << 3);

    float acc[2][4][4];
#pragma unroll
    for (int mt = 0; mt < 2; mt++)
#pragma unroll
        for (int nt = 0; nt < 4; nt++)
#pragma unroll
            for (int e = 0; e < 4; e++) acc[mt][nt][e] = 0.0f;

    LOAD_CHUNK(0);

#pragma unroll 1
    for (int c = 0; c < NCHUNK; c++) {
        __syncthreads();   // previous chunk's mma reads done (and B staging, c=0)
        // Split + store current chunk (8 B stores stay inside one 16 B unit)
#pragma unroll
        for (int j = 0; j < 16; j++) {
            const int row = rbase + j * 8;
            const __nv_bfloat16 h0 = __float2bfloat16(f[j].x);
            const __nv_bfloat16 h1 = __float2bfloat16(f[j].y);
            const __nv_bfloat16 h2 = __float2bfloat16(f[j].z);
            const __nv_bfloat16 h3 = __float2bfloat16(f[j].w);
            const __nv_bfloat16 l0 = __float2bfloat16(f[j].x - __bfloat162float(h0));
            const __nv_bfloat16 l1 = __float2bfloat16(f[j].y - __bfloat162float(h1));
            const __nv_bfloat16 l2 = __float2bfloat16(f[j].z - __bfloat162float(h2));
            const __nv_bfloat16 l3 = __float2bfloat16(f[j].w - __bfloat162float(h3));
            const uint32_t off = sw(((uint32_t)row << 7) + ((uint32_t)seg << 3));
            *(uint2*)(gb + SM_A + off) = make_uint2(pack_bf2(h0, h1), pack_bf2(h2, h3));
            *(uint2*)(gb + SM_A + A_TILE_B + off) = make_uint2(pack_bf2(l0, l1), pack_bf2(l2, l3));
        }
        if (c + 1 < NCHUNK) LOAD_CHUNK(c + 1);   // DRAM latency overlaps mma below
        __syncthreads();

        const uint32_t smA_hi = base + SM_A;
        const uint32_t smA_lo = base + SM_A + A_TILE_B;
        const uint32_t smB_hi = base + SM_B + c * B_TILE_B;
        const uint32_t smB_lo = base + SM_B + (NCHUNK + c) * B_TILE_B;

#pragma unroll
        for (int kg = 0; kg < 4; kg++) {
            uint32_t ah[2][4], al[2][4];
#pragma unroll
            for (int mt = 0; mt < 2; mt++) {
                const uint32_t aoff =
                    sw(((a_row + (uint32_t)(mt * 16)) << 7) + ((kg * 16 + a_ks) << 1));
                LDMX4(ah[mt], smA_hi + aoff);
                LDMX4(al[mt], smA_lo + aoff);
            }
#pragma unroll
            for (int nt = 0; nt < 4; nt++) {
                const uint32_t boff =
                    sw((((uint32_t)(nt * 8) + b_row) << 7) + ((kg * 16 + b_ks) << 1));
                uint32_t bh[2], blr[2];
                LDMX2(bh, smB_hi + boff);
                LDMX2(blr, smB_lo + boff);
#pragma unroll
                for (int mt = 0; mt < 2; mt++) {
                    MMA16816(acc[mt][nt], ah[mt], bh);
                    MMA16816(acc[mt][nt], ah[mt], blr);
                    MMA16816(acc[mt][nt], al[mt], bh);
                }
            }
        }
    }

    // ---- Epilogue: fragment (lane/4, 2*(lane&3)) layout -> float2 stores ----
#pragma unroll
    for (int mt = 0; mt < 2; mt++) {
        const int r0 = v0 + warp_m0 + mt * 16 + (lane >> 2);
#pragma unroll
        for (int nt = 0; nt < 4; nt++) {
            const int cix = nt * 8 + (lane & 3) * 2;
            if (r0 < V_TOK)
                *(float2*)&g_T[(size_t)r0 * H_DIM + cix] =
                    make_float2(acc[mt][nt][0], acc[mt][nt][1]);
            if (r0 + 8 < V_TOK)
                *(float2*)&g_T[(size_t)(r0 + 8) * H_DIM + cix] =
                    make_float2(acc[mt][nt][2], acc[mt][nt][3]);
        }
    }
#undef LOAD_CHUNK
}

// ---------------------------------------------------------------------------
// Kernel B: per batch row b:
//   s[h] = sum_l T[x[b][l]][h];  h = relu(s/len + b1);  out = h @ W2 + b2
// (unchanged — isolates the HMMA GEMM change this round)
// ---------------------------------------------------------------------------
#define ROWS_PER_CTA 2

__global__ __launch_bounds__(256)
void gather_mlp_kernel(const int* __restrict__ x,
                       const int* __restrict__ lengths,
                       const float* __restrict__ b1,
                       const float* __restrict__ W2,
                       const float* __restrict__ b2,
                       float* __restrict__ out) {
    __shared__ int   sidx[ROWS_PER_CTA][L_SEQ];
    __shared__ float psum[8][H_DIM];

    const int tid  = threadIdx.x;
    const int lane = tid & 31;
    const int wid  = tid >> 5;
    const int row  = wid >> 2;
    const int q    = wid & 3;
    const int b    = blockIdx.x * ROWS_PER_CTA + row;

    for (int i = tid; i < ROWS_PER_CTA * L_SEQ; i += 256)
        ((int*)sidx)[i] = x[(size_t)blockIdx.x * ROWS_PER_CTA * L_SEQ + i];
    __syncthreads();

    float acc[10];
#pragma unroll
    for (int u = 0; u < 10; u++) acc[u] = 0.0f;

#pragma unroll 1
    for (int j = 0; j < 5; j++) {
#pragma unroll
        for (int u = 0; u < 10; u++) {
            const int l   = q + 4 * (j * 10 + u);
            const int idx = sidx[row][l];
            acc[u] += __ldg(&g_T[(size_t)idx * H_DIM + lane]);
        }
    }
    float s = ((acc[0] + acc[1]) + (acc[2] + acc[3])) +
              ((acc[4] + acc[5]) + (acc[6] + acc[7])) + (acc[8] + acc[9]);
    psum[wid][lane] = s;
    __syncthreads();

    if (q == 0) {
        const float st = (psum[wid][lane] + psum[wid + 1][lane]) +
                         (psum[wid + 2][lane] + psum[wid + 3][lane]);
        const float len  = (float)__ldg(&lengths[b]);
        const float hval = fmaxf(st / len + __ldg(&b1[lane]), 0.0f);

        float p0 = hval * __ldg(&W2[lane * C_DIM + 0]);
        float p1 = hval * __ldg(&W2[lane * C_DIM + 1]);
        float p2 = hval * __ldg(&W2[lane * C_DIM + 2]);
#pragma unroll
        for (int off = 16; off; off >>= 1) {
            p0 += __shfl_down_sync(0xffffffffu, p0, off);
            p1 += __shfl_down_sync(0xffffffffu, p1, off);
            p2 += __shfl_down_sync(0xffffffffu, p2, off);
        }
        if (lane == 0) {
            out[b * C_DIM + 0] = p0 + __ldg(&b2[0]);
            out[b * C_DIM + 1] = p1 + __ldg(&b2[1]);
            out[b * C_DIM + 2] = p2 + __ldg(&b2[2]);
        }
    }
}

// ---------------------------------------------------------------------------
// Launch: inputs in metadata order: x, lengths, emb_table, W1, b1, W2, b2
// ---------------------------------------------------------------------------
extern "C" void kernel_launch(void* const* d_in, const int* in_sizes, int n_in,
                              void* d_out, int out_size) {
    const int*   x       = (const int*)d_in[0];
    const int*   lengths = (const int*)d_in[1];
    const float* emb     = (const float*)d_in[2];
    const float* W1      = (const float*)d_in[3];
    const float* b1      = (const float*)d_in[4];
    const float* W2      = (const float*)d_in[5];
    const float* b2      = (const float*)d_in[6];
    float*       out     = (float*)d_out;

    (void)in_sizes; (void)n_in; (void)out_size;

    cudaFuncSetAttribute(gemm_T_tensor,
                         cudaFuncAttributeMaxDynamicSharedMemorySize, SM_DYN);
    gemm_T_tensor<<<(V_TOK + M_CTA - 1) / M_CTA, 128, SM_DYN>>>(emb, W1);
    gather_mlp_kernel<<<B_BATCH / ROWS_PER_CTA, 256>>>(x, lengths, b1, W2, b2, out);
}

// round 13
// speedup vs baseline: 3.3524x; 1.0544x over previous
#include <cuda_runtime.h>
#include <cuda_bf16.h>
#include <stdint.h>

// Shapes fixed by the problem definition.
#define V_TOK   50000
#define D_DIM   300
#define H_DIM   32
#define C_DIM   3
#define B_BATCH 2048
#define L_SEQ   200

// Scratch: T = emb_table @ W1, [V_TOK, H_DIM] fp32 (6.4 MB).
__device__ float g_T[V_TOK * H_DIM];
// Pre-built mma.sync B fragments: [split2][chunk5][kg4][nt4][n8][kp4][reg2]
// 10240 words = 40 KB. Lane (n=lane>>2, kp=lane&3) does one LDG.64 per tile.
__device__ uint32_t g_Bfrag[10240];

__device__ __forceinline__ uint32_t smem_u32(const void* p) {
    uint32_t a;
    asm("{ .reg .u64 t; cvta.to.shared.u64 t, %1; cvt.u32.u64 %0, t; }"
        : "=r"(a) : "l"(p));
    return a;
}
// SW128-style XOR swizzle for 128 B rows: bits[6:4] ^= bits[9:7]
__device__ __forceinline__ uint32_t sw(uint32_t off) {
    return off ^ ((off >> 3) & 0x70);
}
__device__ __forceinline__ uint32_t pack_bf2(__nv_bfloat16 lo, __nv_bfloat16 hi) {
    return (uint32_t)__bfloat16_as_ushort(lo) |
           ((uint32_t)__bfloat16_as_ushort(hi) << 16);
}
__device__ __forceinline__ float4 add4(float4 a, float4 b) {
    return make_float4(a.x + b.x, a.y + b.y, a.z + b.z, a.w + b.w);
}

#define LDMX4(r, addr)                                                        \
    asm volatile("ldmatrix.sync.aligned.m8n8.x4.shared.b16 {%0,%1,%2,%3}, [%4];" \
                 : "=r"((r)[0]), "=r"((r)[1]), "=r"((r)[2]), "=r"((r)[3])     \
                 : "r"(addr))
#define MMA16816(d, a, b0, b1)                                                \
    asm volatile("mma.sync.aligned.m16n8k16.row.col.f32.bf16.bf16.f32 "       \
                 "{%0,%1,%2,%3}, {%4,%5,%6,%7}, {%8,%9}, {%0,%1,%2,%3};"      \
                 : "+f"((d)[0]), "+f"((d)[1]), "+f"((d)[2]), "+f"((d)[3])     \
                 : "r"((a)[0]), "r"((a)[1]), "r"((a)[2]), "r"((a)[3]),        \
                   "r"(b0), "r"(b1))

// ===========================================================================
// Kernel A0: build g_Bfrag from W1 (rn 2-way split, mma.sync B layout).
// Flat idx = (((((s*5+c)*4+kg)*4+nt)*8+n)*4+kp)*2+reg
// k = c*64 + kg*16 + kp*2 + reg*8 (and k+1);  n_global = nt*8 + n.
// ===========================================================================
__global__ __launch_bounds__(256)
void conv_B_kernel(const float* __restrict__ W1) {
    const int i = blockIdx.x * 256 + threadIdx.x;
    if (i >= 10240) return;
    const int reg = i & 1;
    const int kp  = (i >> 1) & 3;
    const int n   = (i >> 3) & 7;
    const int nt  = (i >> 6) & 3;
    const int kg  = (i >> 8) & 3;
    const int sc  = i >> 10;        // s*5 + c
    const int c   = sc % 5;
    const int s   = sc / 5;
    const int k   = c * 64 + kg * 16 + kp * 2 + reg * 8;
    const int ng  = nt * 8 + n;
    const float v0 = (k     < D_DIM) ? W1[k * H_DIM + ng]       : 0.0f;
    const float v1 = (k + 1 < D_DIM) ? W1[(k + 1) * H_DIM + ng] : 0.0f;
    const __nv_bfloat16 h0 = __float2bfloat16(v0);
    const __nv_bfloat16 h1 = __float2bfloat16(v1);
    __nv_bfloat16 e0, e1;
    if (s == 0) { e0 = h0; e1 = h1; }
    else {
        e0 = __float2bfloat16(v0 - __bfloat162float(h0));
        e1 = __float2bfloat16(v1 - __bfloat162float(h1));
    }
    g_Bfrag[i] = pack_bf2(e0, e1);
}

// ===========================================================================
// Kernel A: T = emb @ W1 via bf16 HMMA with 2-way split
//   D = Ahi*Bhi + Ahi*Blo + Alo*Bhi   (fp32 accumulate)
// A-hi via PRMT mantissa-truncate (residual exact in lo), lo via cvt.bf16x2.
// Double-buffered A smem + single sync/chunk pipeline:
//   sync; STS(c+1 -> buf^1); LDG(c+2 -> regs); mma(c, buf)
// B fragments streamed from g_Bfrag (warm L1 broadcast), no B smem.
// ===========================================================================
#define M_CTA    128
#define KCH      64
#define NCHUNK   5
#define A_TILE_B (M_CTA * KCH * 2)          // 16384 B per (buf, split)
#define SM_NEED  (4 * A_TILE_B)             // 65536
#define SM_DYN   (SM_NEED + 1024)

extern __shared__ char dyn_smem[];

__global__ __launch_bounds__(128)
void gemm_T_tensor(const float* __restrict__ emb) {
    const uint32_t raw  = smem_u32(dyn_smem);
    const uint32_t base = (raw + 1023u) & ~1023u;
    char* const gb      = dyn_smem + (base - raw);

    const int tid  = threadIdx.x;
    const int lane = tid & 31;
    const int wid  = tid >> 5;
    const int v0   = blockIdx.x * M_CTA;

    const int seg   = tid & 15;      // k seg (4 floats)
    const int rbase = tid >> 4;      // row base, j strides 8

    float4 f[16];
#define LOAD_CHUNK(c)                                                          \
    do {                                                                       \
        const int k0 = (c) * KCH + seg * 4;                                    \
        const bool kok = (k0 < D_DIM);                                         \
        _Pragma("unroll")                                                      \
        for (int j = 0; j < 16; j++) {                                         \
            const int v = v0 + rbase + j * 8;                                  \
            f[j] = (kok && v < V_TOK)                                          \
                 ? *(const float4*)(emb + (size_t)v * D_DIM + k0)              \
                 : make_float4(0.f, 0.f, 0.f, 0.f);                            \
        }                                                                      \
    } while (0)

    // A split + store into buffer bu (hi at (bu*2), lo at (bu*2+1))
#define CONV_STS(bu)                                                           \
    do {                                                                       \
        char* const Ahi = gb + ((bu) * 2 + 0) * A_TILE_B;                      \
        char* const Alo = gb + ((bu) * 2 + 1) * A_TILE_B;                      \
        _Pragma("unroll")                                                      \
        for (int j = 0; j < 16; j++) {                                         \
            const int row = rbase + j * 8;                                     \
            const uint32_t xb = __float_as_uint(f[j].x);                       \
            const uint32_t yb = __float_as_uint(f[j].y);                       \
            const uint32_t zb = __float_as_uint(f[j].z);                       \
            const uint32_t wb = __float_as_uint(f[j].w);                       \
            uint32_t hi01, hi23;                                               \
            asm("prmt.b32 %0, %1, %2, 0x7632;" : "=r"(hi01) : "r"(xb), "r"(yb)); \
            asm("prmt.b32 %0, %1, %2, 0x7632;" : "=r"(hi23) : "r"(zb), "r"(wb)); \
            const float lx = f[j].x - __uint_as_float(xb & 0xFFFF0000u);       \
            const float ly = f[j].y - __uint_as_float(yb & 0xFFFF0000u);       \
            const float lz = f[j].z - __uint_as_float(zb & 0xFFFF0000u);       \
            const float lw = f[j].w - __uint_as_float(wb & 0xFFFF0000u);       \
            uint32_t lo01, lo23;                                               \
            asm("cvt.rn.bf16x2.f32 %0, %1, %2;" : "=r"(lo01) : "f"(ly), "f"(lx)); \
            asm("cvt.rn.bf16x2.f32 %0, %1, %2;" : "=r"(lo23) : "f"(lw), "f"(lz)); \
            const uint32_t off = sw(((uint32_t)row << 7) + ((uint32_t)seg << 3)); \
            *(uint2*)(Ahi + off) = make_uint2(hi01, hi23);                     \
            *(uint2*)(Alo + off) = make_uint2(lo01, lo23);                     \
        }                                                                      \
    } while (0)

    // ldmatrix A per-lane address components
    const int warp_m0    = wid * 32;
    const uint32_t a_row = (uint32_t)(warp_m0 + (lane & 15));
    const uint32_t a_ks  = (uint32_t)((lane >> 4) << 3);   // 0 or 8
    // B fragment per-lane offset
    const int boff = (lane >> 2) * 8 + (lane & 3) * 2;

    float acc[2][4][4];
#pragma unroll
    for (int mt = 0; mt < 2; mt++)
#pragma unroll
        for (int nt = 0; nt < 4; nt++)
#pragma unroll
            for (int e = 0; e < 4; e++) acc[mt][nt][e] = 0.0f;

    LOAD_CHUNK(0);
    CONV_STS(0);
    LOAD_CHUNK(1);

#pragma unroll 1
    for (int c = 0; c < NCHUNK; c++) {
        const int buf = c & 1;
        __syncthreads();                 // STS(c) visible; ldmatrix(c-1) drained
        if (c + 1 < NCHUNK) CONV_STS(buf ^ 1);   // f = chunk c+1
        if (c + 2 < NCHUNK) LOAD_CHUNK(c + 2);   // DRAM overlaps mma below

        const uint32_t smA_hi = base + (buf * 2 + 0) * A_TILE_B;
        const uint32_t smA_lo = base + (buf * 2 + 1) * A_TILE_B;

#pragma unroll
        for (int kg = 0; kg < 4; kg++) {
            uint32_t ah[2][4], al[2][4];
#pragma unroll
            for (int mt = 0; mt < 2; mt++) {
                const uint32_t aoff =
                    sw(((a_row + (uint32_t)(mt * 16)) << 7) + ((kg * 16 + a_ks) << 1));
                LDMX4(ah[mt], smA_hi + aoff);
                LDMX4(al[mt], smA_lo + aoff);
            }
            // B fragments for this kg (batched: MLP 8, warm L1 broadcast)
            uint2 bh[4], bl[4];
            const int th = ((0 * NCHUNK + c) * 4 + kg) * 4;  // hi tile base
            const int tl = ((1 * NCHUNK + c) * 4 + kg) * 4;  // lo tile base
#pragma unroll
            for (int nt = 0; nt < 4; nt++) {
                bh[nt] = *(const uint2*)&g_Bfrag[(th + nt) * 64 + boff];
                bl[nt] = *(const uint2*)&g_Bfrag[(tl + nt) * 64 + boff];
            }
#pragma unroll
            for (int nt = 0; nt < 4; nt++) {
#pragma unroll
                for (int mt = 0; mt < 2; mt++) {
                    MMA16816(acc[mt][nt], ah[mt], bh[nt].x, bh[nt].y);
                    MMA16816(acc[mt][nt], ah[mt], bl[nt].x, bl[nt].y);
                    MMA16816(acc[mt][nt], al[mt], bh[nt].x, bh[nt].y);
                }
            }
        }
    }

    // ---- Epilogue: fragment (lane/4, 2*(lane&3)) layout -> float2 stores ----
#pragma unroll
    for (int mt = 0; mt < 2; mt++) {
        const int r0 = v0 + warp_m0 + mt * 16 + (lane >> 2);
#pragma unroll
        for (int nt = 0; nt < 4; nt++) {
            const int cix = nt * 8 + (lane & 3) * 2;
            if (r0 < V_TOK)
                *(float2*)&g_T[(size_t)r0 * H_DIM + cix] =
                    make_float2(acc[mt][nt][0], acc[mt][nt][1]);
            if (r0 + 8 < V_TOK)
                *(float2*)&g_T[(size_t)(r0 + 8) * H_DIM + cix] =
                    make_float2(acc[mt][nt][2], acc[mt][nt][3]);
        }
    }
#undef LOAD_CHUNK
#undef CONV_STS
}

// ---------------------------------------------------------------------------
// Kernel B: s[h] = sum_l T[x[b][l]][h]; h = relu(s/len + b1); out = h@W2 + b2
// CTA = 256 thr = 8 warps = 4 rows x 2 half-warps. Lane = (t = lane>>3 token
// quad, hq = lane&7 h-quad). One LDG.128 per lane covers 4 tokens x 32 h per
// warp-iteration (3x fewer instructions/token than R12); 2 float4 acc chains.
// Cross-t reduce via shfl, halves combined in smem, then W2 epilogue.
// ---------------------------------------------------------------------------
#define ROWS_PER_CTA 4

__global__ __launch_bounds__(256)
void gather_mlp_kernel(const int* __restrict__ x,
                       const int* __restrict__ lengths,
                       const float* __restrict__ b1,
                       const float* __restrict__ W2,
                       const float* __restrict__ b2,
                       float* __restrict__ out) {
    __shared__ int   sidx[ROWS_PER_CTA][L_SEQ];
    __shared__ float psum[8][H_DIM];

    const int tid  = threadIdx.x;
    const int lane = tid & 31;
    const int wid  = tid >> 5;
    const int row  = wid >> 1;        // 0..3 CTA-local batch row
    const int half = wid & 1;         // l parity

    for (int i = tid; i < ROWS_PER_CTA * L_SEQ; i += 256)
        ((int*)sidx)[i] = x[(size_t)blockIdx.x * ROWS_PER_CTA * L_SEQ + i];
    __syncthreads();

    const int t  = lane >> 3;         // token slot in iteration
    const int hq = lane & 7;          // h quad

    float4 a0 = make_float4(0.f, 0.f, 0.f, 0.f);
    float4 a1 = make_float4(0.f, 0.f, 0.f, 0.f);
#pragma unroll
    for (int i = 0; i < 24; i += 2) {
        const int i0 = sidx[row][half + 2 * (i * 4 + t)];
        const int i1 = sidx[row][half + 2 * ((i + 1) * 4 + t)];
        const float4 v0 = __ldg((const float4*)&g_T[(size_t)i0 * H_DIM + hq * 4]);
        const float4 v1 = __ldg((const float4*)&g_T[(size_t)i1 * H_DIM + hq * 4]);
        a0 = add4(a0, v0);
        a1 = add4(a1, v1);
    }
    {   // i = 24 (25 iterations total: 25*4 = 100 tokens per warp)
        const int i0 = sidx[row][half + 2 * (24 * 4 + t)];
        a0 = add4(a0, __ldg((const float4*)&g_T[(size_t)i0 * H_DIM + hq * 4]));
    }
    float4 s = add4(a0, a1);
    // reduce over t (strides 16, 8): lanes 0..7 end with full sums for their hq
#pragma unroll
    for (int off = 16; off >= 8; off >>= 1) {
        s.x += __shfl_down_sync(0xffffffffu, s.x, off);
        s.y += __shfl_down_sync(0xffffffffu, s.y, off);
        s.z += __shfl_down_sync(0xffffffffu, s.z, off);
        s.w += __shfl_down_sync(0xffffffffu, s.w, off);
    }
    if (lane < 8)
        *(float4*)&psum[wid][lane * 4] = s;
    __syncthreads();

    if (half == 0) {
        const int b = blockIdx.x * ROWS_PER_CTA + row;
        const float st = psum[wid][lane] + psum[wid + 1][lane];
        const float len  = (float)__ldg(&lengths[b]);
        const float hval = fmaxf(st / len + __ldg(&b1[lane]), 0.0f);

        float p0 = hval * __ldg(&W2[lane * C_DIM + 0]);
        float p1 = hval * __ldg(&W2[lane * C_DIM + 1]);
        float p2 = hval * __ldg(&W2[lane * C_DIM + 2]);
#pragma unroll
        for (int off = 16; off; off >>= 1) {
            p0 += __shfl_down_sync(0xffffffffu, p0, off);
            p1 += __shfl_down_sync(0xffffffffu, p1, off);
            p2 += __shfl_down_sync(0xffffffffu, p2, off);
        }
        if (lane == 0) {
            out[b * C_DIM + 0] = p0 + __ldg(&b2[0]);
            out[b * C_DIM + 1] = p1 + __ldg(&b2[1]);
            out[b * C_DIM + 2] = p2 + __ldg(&b2[2]);
        }
    }
}

// ---------------------------------------------------------------------------
// Launch: inputs in metadata order: x, lengths, emb_table, W1, b1, W2, b2
// ---------------------------------------------------------------------------
extern "C" void kernel_launch(void* const* d_in, const int* in_sizes, int n_in,
                              void* d_out, int out_size) {
    const int*   x       = (const int*)d_in[0];
    const int*   lengths = (const int*)d_in[1];
    const float* emb     = (const float*)d_in[2];
    const float* W1      = (const float*)d_in[3];
    const float* b1      = (const float*)d_in[4];
    const float* W2      = (const float*)d_in[5];
    const float* b2      = (const float*)d_in[6];
    float*       out     = (float*)d_out;

    (void)in_sizes; (void)n_in; (void)out_size;

    conv_B_kernel<<<40, 256>>>(W1);
    cudaFuncSetAttribute(gemm_T_tensor,
                         cudaFuncAttributeMaxDynamicSharedMemorySize, SM_DYN);
    gemm_T_tensor<<<(V_TOK + M_CTA - 1) / M_CTA, 128, SM_DYN>>>(emb);
    gather_mlp_kernel<<<B_BATCH / ROWS_PER_CTA, 256>>>(x, lengths, b1, W2, b2, out);
}

// round 14
// speedup vs baseline: 3.3750x; 1.0067x over previous
#include <cuda_runtime.h>
#include <cuda_bf16.h>
#include <stdint.h>

// Shapes fixed by the problem definition.
#define V_TOK   50000
#define D_DIM   300
#define H_DIM   32
#define C_DIM   3
#define B_BATCH 2048
#define L_SEQ   200

// Scratch: T = emb_table @ W1, [V_TOK, H_DIM] fp32 (6.4 MB).
__device__ float g_T[V_TOK * H_DIM];
// Pre-built mma.sync B fragments: [split2][chunk10][kg2][nt4][64 words].
// Word within tile = n*8 + kp*2 + reg;  lane (n=lane>>2, kp=lane&3) -> LDG.64.
__device__ uint32_t g_Bfrag[10240];

__device__ __forceinline__ uint32_t smem_u32(const void* p) {
    uint32_t a;
    asm("{ .reg .u64 t; cvta.to.shared.u64 t, %1; cvt.u32.u64 %0, t; }"
        : "=r"(a) : "l"(p));
    return a;
}
// SW64 swizzle for 64 B rows: bits[5:4] ^= bits[8:7]
__device__ __forceinline__ uint32_t sw64(uint32_t off) {
    return off ^ ((off >> 3) & 0x30);
}
__device__ __forceinline__ uint32_t pack_bf2(__nv_bfloat16 lo, __nv_bfloat16 hi) {
    return (uint32_t)__bfloat16_as_ushort(lo) |
           ((uint32_t)__bfloat16_as_ushort(hi) << 16);
}
__device__ __forceinline__ float4 add4(float4 a, float4 b) {
    return make_float4(a.x + b.x, a.y + b.y, a.z + b.z, a.w + b.w);
}

#define LDMX4(r, addr)                                                        \
    asm volatile("ldmatrix.sync.aligned.m8n8.x4.shared.b16 {%0,%1,%2,%3}, [%4];" \
                 : "=r"((r)[0]), "=r"((r)[1]), "=r"((r)[2]), "=r"((r)[3])     \
                 : "r"(addr))
#define MMA16816(d, a, b0, b1)                                                \
    asm volatile("mma.sync.aligned.m16n8k16.row.col.f32.bf16.bf16.f32 "       \
                 "{%0,%1,%2,%3}, {%4,%5,%6,%7}, {%8,%9}, {%0,%1,%2,%3};"      \
                 : "+f"((d)[0]), "+f"((d)[1]), "+f"((d)[2]), "+f"((d)[3])     \
                 : "r"((a)[0]), "r"((a)[1]), "r"((a)[2]), "r"((a)[3]),        \
                   "r"(b0), "r"(b1))

// ===========================================================================
// Kernel A0: build g_Bfrag from W1. Grid 40 = (s2, c10, kg2) exactly;
// block 256 = (nt,n,kp,reg). W1 slice (16 k x 32 n) staged in smem coalesced;
// no integer div/mod; output store fully coalesced: idx = bid*256 + tid.
// k = c*32 + kg*16 + kp*2 + reg*8 (and k+1); n_global = nt*8 + n.
// ===========================================================================
__global__ __launch_bounds__(256)
void conv_B_kernel(const float* __restrict__ W1) {
    __shared__ float ws[16][H_DIM];
    const int tid = threadIdx.x;
    const int bid = blockIdx.x;             // (s*10 + c)*2 + kg
    const int kg  = bid & 1;
    const int s   = (bid >> 1) >= 10;
    const int c   = (bid >> 1) - s * 10;
    const int kbase = c * 32 + kg * 16;

    for (int i = tid; i < 16 * H_DIM; i += 256) {
        const int kk = i >> 5;
        const int n  = i & 31;
        ws[kk][n] = (kbase + kk < D_DIM) ? W1[(kbase + kk) * H_DIM + n] : 0.0f;
    }
    __syncthreads();

    const int reg = tid & 1;
    const int kp  = (tid >> 1) & 3;
    const int n   = (tid >> 3) & 7;
    const int nt  = tid >> 6;
    const int kk0 = kp * 2 + reg * 8;
    const int ng  = nt * 8 + n;

    const float v0 = ws[kk0][ng];
    const float v1 = ws[kk0 + 1][ng];
    __nv_bfloat16 e0, e1;
    if (s == 0) {
        e0 = __float2bfloat16(v0);
        e1 = __float2bfloat16(v1);
    } else {
        e0 = __float2bfloat16(v0 - __bfloat162float(__float2bfloat16(v0)));
        e1 = __float2bfloat16(v1 - __bfloat162float(__float2bfloat16(v1)));
    }
    g_Bfrag[bid * 256 + tid] = pack_bf2(e0, e1);
}

// ===========================================================================
// Kernel A: T = emb @ W1 via bf16 HMMA with 2-way split
//   D = Ahi*Bhi + Ahi*Blo + Alo*Bhi   (fp32 accumulate)
// KCH=32 (10 chunks): A tile 8 KB/split, 4 buffers = 32 KB smem ->
// 5 CTAs/SM (20 warps/SM), grid 391 = single wave of 740 slots.
// Pipeline per chunk: sync; STS(c+1 -> buf^1); LDG(c+2 -> regs); mma(c, buf).
// A rows are 64 B -> SW64 swizzle (bank-clean for STS.64 stage + ldmatrix).
// B fragments streamed from g_Bfrag (warm L1 broadcast), no B smem.
// ===========================================================================
#define M_CTA    128
#define KCH      32
#define NCHUNK   10
#define A_TILE_B (M_CTA * KCH * 2)          // 8192 B per (buf, split)
#define SM_NEED  (4 * A_TILE_B)             // 32768
#define SM_DYN   (SM_NEED + 1024)

extern __shared__ char dyn_smem[];

__global__ __launch_bounds__(128, 5)
void gemm_T_tensor(const float* __restrict__ emb) {
    const uint32_t raw  = smem_u32(dyn_smem);
    const uint32_t base = (raw + 1023u) & ~1023u;
    char* const gb      = dyn_smem + (base - raw);

    const int tid  = threadIdx.x;
    const int lane = tid & 31;
    const int wid  = tid >> 5;
    const int v0   = blockIdx.x * M_CTA;

    const int seg   = tid & 7;       // k seg (4 floats, 32 floats/row)
    const int rbase = tid >> 3;      // row base, j strides 16

    float4 f[8];
#define LOAD_CHUNK(c)                                                          \
    do {                                                                       \
        const int k0 = (c) * KCH + seg * 4;                                    \
        const bool kok = (k0 < D_DIM);                                         \
        _Pragma("unroll")                                                      \
        for (int j = 0; j < 8; j++) {                                          \
            const int v = v0 + rbase + j * 16;                                 \
            f[j] = (kok && v < V_TOK)                                          \
                 ? *(const float4*)(emb + (size_t)v * D_DIM + k0)              \
                 : make_float4(0.f, 0.f, 0.f, 0.f);                            \
        }                                                                      \
    } while (0)

#define CONV_STS(bu)                                                           \
    do {                                                                       \
        char* const Ahi = gb + ((bu) * 2 + 0) * A_TILE_B;                      \
        char* const Alo = gb + ((bu) * 2 + 1) * A_TILE_B;                      \
        _Pragma("unroll")                                                      \
        for (int j = 0; j < 8; j++) {                                          \
            const int row = rbase + j * 16;                                    \
            const uint32_t xb = __float_as_uint(f[j].x);                       \
            const uint32_t yb = __float_as_uint(f[j].y);                       \
            const uint32_t zb = __float_as_uint(f[j].z);                       \
            const uint32_t wb = __float_as_uint(f[j].w);                       \
            uint32_t hi01, hi23;                                               \
            asm("prmt.b32 %0, %1, %2, 0x7632;" : "=r"(hi01) : "r"(xb), "r"(yb)); \
            asm("prmt.b32 %0, %1, %2, 0x7632;" : "=r"(hi23) : "r"(zb), "r"(wb)); \
            const float lx = f[j].x - __uint_as_float(xb & 0xFFFF0000u);       \
            const float ly = f[j].y - __uint_as_float(yb & 0xFFFF0000u);       \
            const float lz = f[j].z - __uint_as_float(zb & 0xFFFF0000u);       \
            const float lw = f[j].w - __uint_as_float(wb & 0xFFFF0000u);       \
            uint32_t lo01, lo23;                                               \
            asm("cvt.rn.bf16x2.f32 %0, %1, %2;" : "=r"(lo01) : "f"(ly), "f"(lx)); \
            asm("cvt.rn.bf16x2.f32 %0, %1, %2;" : "=r"(lo23) : "f"(lw), "f"(lz)); \
            const uint32_t off = sw64(((uint32_t)row << 6) + ((uint32_t)seg << 3)); \
            *(uint2*)(Ahi + off) = make_uint2(hi01, hi23);                     \
            *(uint2*)(Alo + off) = make_uint2(lo01, lo23);                     \
        }                                                                      \
    } while (0)

    // ldmatrix A per-lane address components
    const int warp_m0    = wid * 32;
    const uint32_t a_row = (uint32_t)(warp_m0 + (lane & 15));
    const uint32_t a_ks  = (uint32_t)((lane >> 4) << 3);   // 0 or 8
    // B fragment per-lane offset
    const int boff = (lane >> 2) * 8 + (lane & 3) * 2;

    float acc[2][4][4];
#pragma unroll
    for (int mt = 0; mt < 2; mt++)
#pragma unroll
        for (int nt = 0; nt < 4; nt++)
#pragma unroll
            for (int e = 0; e < 4; e++) acc[mt][nt][e] = 0.0f;

    LOAD_CHUNK(0);
    CONV_STS(0);
    LOAD_CHUNK(1);

#pragma unroll 1
    for (int c = 0; c < NCHUNK; c++) {
        const int buf = c & 1;
        __syncthreads();                 // STS(c) visible; ldmatrix(c-1) drained
        if (c + 1 < NCHUNK) CONV_STS(buf ^ 1);   // f = chunk c+1
        if (c + 2 < NCHUNK) LOAD_CHUNK(c + 2);   // DRAM overlaps mma below

        const uint32_t smA_hi = base + (buf * 2 + 0) * A_TILE_B;
        const uint32_t smA_lo = base + (buf * 2 + 1) * A_TILE_B;

#pragma unroll
        for (int kg = 0; kg < 2; kg++) {
            uint32_t ah[2][4], al[2][4];
#pragma unroll
            for (int mt = 0; mt < 2; mt++) {
                const uint32_t aoff =
                    sw64(((a_row + (uint32_t)(mt * 16)) << 6) + ((kg * 16 + a_ks) << 1));
                LDMX4(ah[mt], smA_hi + aoff);
                LDMX4(al[mt], smA_lo + aoff);
            }
            uint2 bh[4], bl[4];
            const int th = ((0 * NCHUNK + c) * 2 + kg) * 4;  // hi tile base
            const int tl = ((1 * NCHUNK + c) * 2 + kg) * 4;  // lo tile base
#pragma unroll
            for (int nt = 0; nt < 4; nt++) {
                bh[nt] = *(const uint2*)&g_Bfrag[(th + nt) * 64 + boff];
                bl[nt] = *(const uint2*)&g_Bfrag[(tl + nt) * 64 + boff];
            }
#pragma unroll
            for (int nt = 0; nt < 4; nt++) {
#pragma unroll
                for (int mt = 0; mt < 2; mt++) {
                    MMA16816(acc[mt][nt], ah[mt], bh[nt].x, bh[nt].y);
                    MMA16816(acc[mt][nt], ah[mt], bl[nt].x, bl[nt].y);
                    MMA16816(acc[mt][nt], al[mt], bh[nt].x, bh[nt].y);
                }
            }
        }
    }

    // ---- Epilogue: fragment (lane/4, 2*(lane&3)) layout -> float2 stores ----
#pragma unroll
    for (int mt = 0; mt < 2; mt++) {
        const int r0 = v0 + warp_m0 + mt * 16 + (lane >> 2);
#pragma unroll
        for (int nt = 0; nt < 4; nt++) {
            const int cix = nt * 8 + (lane & 3) * 2;
            if (r0 < V_TOK)
                *(float2*)&g_T[(size_t)r0 * H_DIM + cix] =
                    make_float2(acc[mt][nt][0], acc[mt][nt][1]);
            if (r0 + 8 < V_TOK)
                *(float2*)&g_T[(size_t)(r0 + 8) * H_DIM + cix] =
                    make_float2(acc[mt][nt][2], acc[mt][nt][3]);
        }
    }
#undef LOAD_CHUNK
#undef CONV_STS
}

// ---------------------------------------------------------------------------
// Kernel B: s[h] = sum_l T[x[b][l]][h]; h = relu(s/len + b1); out = h@W2 + b2
// (unchanged from R13 — isolates the gemm/conv changes this round)
// ---------------------------------------------------------------------------
#define ROWS_PER_CTA 4

__global__ __launch_bounds__(256)
void gather_mlp_kernel(const int* __restrict__ x,
                       const int* __restrict__ lengths,
                       const float* __restrict__ b1,
                       const float* __restrict__ W2,
                       const float* __restrict__ b2,
                       float* __restrict__ out) {
    __shared__ int   sidx[ROWS_PER_CTA][L_SEQ];
    __shared__ float psum[8][H_DIM];

    const int tid  = threadIdx.x;
    const int lane = tid & 31;
    const int wid  = tid >> 5;
    const int row  = wid >> 1;
    const int half = wid & 1;

    for (int i = tid; i < ROWS_PER_CTA * L_SEQ; i += 256)
        ((int*)sidx)[i] = x[(size_t)blockIdx.x * ROWS_PER_CTA * L_SEQ + i];
    __syncthreads();

    const int t  = lane >> 3;
    const int hq = lane & 7;

    float4 a0 = make_float4(0.f, 0.f, 0.f, 0.f);
    float4 a1 = make_float4(0.f, 0.f, 0.f, 0.f);
#pragma unroll
    for (int i = 0; i < 24; i += 2) {
        const int i0 = sidx[row][half + 2 * (i * 4 + t)];
        const int i1 = sidx[row][half + 2 * ((i + 1) * 4 + t)];
        a0 = add4(a0, __ldg((const float4*)&g_T[(size_t)i0 * H_DIM + hq * 4]));
        a1 = add4(a1, __ldg((const float4*)&g_T[(size_t)i1 * H_DIM + hq * 4]));
    }
    {
        const int i0 = sidx[row][half + 2 * (24 * 4 + t)];
        a0 = add4(a0, __ldg((const float4*)&g_T[(size_t)i0 * H_DIM + hq * 4]));
    }
    float4 s = add4(a0, a1);
#pragma unroll
    for (int off = 16; off >= 8; off >>= 1) {
        s.x += __shfl_down_sync(0xffffffffu, s.x, off);
        s.y += __shfl_down_sync(0xffffffffu, s.y, off);
        s.z += __shfl_down_sync(0xffffffffu, s.z, off);
        s.w += __shfl_down_sync(0xffffffffu, s.w, off);
    }
    if (lane < 8)
        *(float4*)&psum[wid][lane * 4] = s;
    __syncthreads();

    if (half == 0) {
        const int b = blockIdx.x * ROWS_PER_CTA + row;
        const float st = psum[wid][lane] + psum[wid + 1][lane];
        const float len  = (float)__ldg(&lengths[b]);
        const float hval = fmaxf(st / len + __ldg(&b1[lane]), 0.0f);

        float p0 = hval * __ldg(&W2[lane * C_DIM + 0]);
        float p1 = hval * __ldg(&W2[lane * C_DIM + 1]);
        float p2 = hval * __ldg(&W2[lane * C_DIM + 2]);
#pragma unroll
        for (int off = 16; off; off >>= 1) {
            p0 += __shfl_down_sync(0xffffffffu, p0, off);
            p1 += __shfl_down_sync(0xffffffffu, p1, off);
            p2 += __shfl_down_sync(0xffffffffu, p2, off);
        }
        if (lane == 0) {
            out[b * C_DIM + 0] = p0 + __ldg(&b2[0]);
            out[b * C_DIM + 1] = p1 + __ldg(&b2[1]);
            out[b * C_DIM + 2] = p2 + __ldg(&b2[2]);
        }
    }
}

// ---------------------------------------------------------------------------
// Launch: inputs in metadata order: x, lengths, emb_table, W1, b1, W2, b2
// ---------------------------------------------------------------------------
extern "C" void kernel_launch(void* const* d_in, const int* in_sizes, int n_in,
                              void* d_out, int out_size) {
    const int*   x       = (const int*)d_in[0];
    const int*   lengths = (const int*)d_in[1];
    const float* emb     = (const float*)d_in[2];
    const float* W1      = (const float*)d_in[3];
    const float* b1      = (const float*)d_in[4];
    const float* W2      = (const float*)d_in[5];
    const float* b2      = (const float*)d_in[6];
    float*       out     = (float*)d_out;

    (void)in_sizes; (void)n_in; (void)out_size;

    conv_B_kernel<<<40, 256>>>(W1);
    cudaFuncSetAttribute(gemm_T_tensor,
                         cudaFuncAttributeMaxDynamicSharedMemorySize, SM_DYN);
    gemm_T_tensor<<<(V_TOK + M_CTA - 1) / M_CTA, 128, SM_DYN>>>(emb);
    gather_mlp_kernel<<<B_BATCH / ROWS_PER_CTA, 256>>>(x, lengths, b1, W2, b2, out);
}